// round 7
// baseline (speedup 1.0000x reference)
#include <cuda_runtime.h>
#include <cuda_fp16.h>
#include <cstdint>
#include <cstddef>

// problem constants
#define NIN   1152
#define NOUT  10
#define DIN   8
#define DOUT  16
#define BB    256
#define JO    160
#define KD    9216
#define IJ    11520
#define KSPLIT 32
#define KCHUNK 288
#define NB    128            // persistent grid size (< 148 SMs -> co-resident)

// Row index convention for the contraction dim: r = i*8 + d  (capsule-major).
__device__ __half g_xh[(size_t)BB * KD];      // [b][r]
__device__ __half g_xt[(size_t)KD * BB];      // [r][b]
__device__ __half g_wt[(size_t)KD * JO];      // [r][jo]  unscaled W
__device__ __half g_wc[(size_t)KD * JO];      // [r][jo]  c-scaled W (per iter)
__device__ __half g_vh[BB * JO];              // [b][jo]
__device__ float  g_s[BB * JO];               // s accumulator (RED target)
__device__ float  g_blog[IJ];

// grid barrier state (sense-reversal via generation counter)
__device__ unsigned int          g_bar_cnt;   // zero-initialized
__device__ volatile unsigned int g_bar_gen;   // zero-initialized

__device__ __forceinline__ void grid_barrier() {
    __threadfence();
    __syncthreads();
    if (threadIdx.x == 0) {
        unsigned int gen = g_bar_gen;
        unsigned int arr = atomicAdd(&g_bar_cnt, 1u);
        if (arr == (unsigned int)(NB - 1)) {
            atomicExch(&g_bar_cnt, 0u);
            __threadfence();
            g_bar_gen = gen + 1u;
        } else {
            while (g_bar_gen == gen) {
                __nanosleep(64);
            }
        }
        __threadfence();
    }
    __syncthreads();
}

__device__ __forceinline__ unsigned int smem_u32(const void* p) {
    return (unsigned int)__cvta_generic_to_shared(p);
}

__device__ __forceinline__ void ldsm_x4(unsigned int& r0, unsigned int& r1,
                                        unsigned int& r2, unsigned int& r3,
                                        unsigned int addr) {
    asm volatile("ldmatrix.sync.aligned.m8n8.x4.shared.b16 {%0,%1,%2,%3}, [%4];"
                 : "=r"(r0), "=r"(r1), "=r"(r2), "=r"(r3) : "r"(addr));
}

__device__ __forceinline__ void ldsm_x2t(unsigned int& r0, unsigned int& r1,
                                         unsigned int addr) {
    asm volatile("ldmatrix.sync.aligned.m8n8.x2.trans.shared.b16 {%0,%1}, [%2];"
                 : "=r"(r0), "=r"(r1) : "r"(addr));
}

__device__ __forceinline__ void mma16816(float* c,
                                         unsigned int a0, unsigned int a1,
                                         unsigned int a2, unsigned int a3,
                                         unsigned int b0, unsigned int b1) {
    asm volatile(
        "mma.sync.aligned.m16n8k16.row.col.f32.f16.f16.f32 "
        "{%0,%1,%2,%3}, {%4,%5,%6,%7}, {%8,%9}, {%0,%1,%2,%3};"
        : "+f"(c[0]), "+f"(c[1]), "+f"(c[2]), "+f"(c[3])
        : "r"(a0), "r"(a1), "r"(a2), "r"(a3), "r"(b0), "r"(b1));
}

// Shared memory layout (byte offsets into one 12.8 KB buffer):
//   P0: tile (32x33 f32, 4224B at 0) / sh (1280 f32, 5120B at 0)
//   P1: As 64x24 half at 0 (3072B); Bs 16x168 half at 3072 (5376B)
//   P2: red 160 f32 at 0
//   P3: As 128x24 half at 0 (6144B); Bs at 6144 (5376B);
//       sa 160 f32 at 11520; sc 160 f32 at 12160
#define SMEM_BYTES 12800

__global__ __launch_bounds__(256, 1) void k_mega(const float* __restrict__ x,
                                                 const float* __restrict__ w,
                                                 float* __restrict__ out) {
    __shared__ __align__(16) unsigned char smbuf[SMEM_BYTES];
    const int blk = blockIdx.x;
    const int t = threadIdx.x;
    const int lane = t & 31;
    const int wid = t >> 5;

    // ================= P0: prep =================
    {
        // x: 2304 tiles of 32x32; 18 tiles per block.
        float (*tile)[33] = (float (*)[33])smbuf;
        const int tx = lane;
        const int ty = wid;              // 0..7
        for (int q = 0; q < 18; q++) {
            int tl = blk + q * NB;
            int txi = tl % 288;
            int tyb = tl / 288;
            int di0 = txi * 32;
            int b0 = tyb * 32;
            int d = di0 / NIN;
            int ibase = di0 - d * NIN;
            __syncthreads();
            #pragma unroll
            for (int qq = 0; qq < 4; qq++) {
                int r = ty + qq * 8;
                float v = x[(size_t)(b0 + r) * KD + di0 + tx];
                tile[r][tx] = v;
                g_xh[(size_t)(b0 + r) * KD + (ibase + tx) * 8 + d] = __float2half(v);
            }
            __syncthreads();
            #pragma unroll
            for (int qq = 0; qq < 4; qq++) {
                int r = ty + qq * 8;
                g_xt[(size_t)((ibase + r) * 8 + d) * BB + b0 + tx] =
                    __float2half(tile[tx][r]);
            }
        }
        // w: 9 capsules per block.
        float* sh = (float*)smbuf;
        for (int q = 0; q < 9; q++) {
            int i = blk * 9 + q;
            __syncthreads();
            #pragma unroll
            for (int qq = 0; qq < 5; qq++) {
                sh[t + qq * 256] = w[(size_t)i * 1280 + t + qq * 256];
            }
            __syncthreads();
            if (t < 160) {
                #pragma unroll
                for (int d = 0; d < 8; d++) {
                    float raw = sh[(t >> 4) * 128 + (t & 15) * 8 + d];
                    g_wt[(size_t)(i * 8 + d) * JO + t] = __float2half(raw);
                    g_wc[(size_t)(i * 8 + d) * JO + t] = __float2half(0.1f * raw);
                }
                if (t < 10) g_blog[i * 10 + t] = 0.f;
            }
        }
        // zero s accumulator: 320 floats per block.
        for (int q = t; q < 320; q += 256) g_s[blk * 320 + q] = 0.f;
    }
    grid_barrier();

    for (int it = 0; it < 3; it++) {
        // ================= P1: gemm_s =================
        {
            __half* As = (__half*)smbuf;
            __half* Bs = (__half*)(smbuf + 3072);
            const int split = blk >> 2;
            const int m0 = (blk & 3) * 64;
            const int kbase = split * KCHUNK;
            const int wr = wid & 3;
            const int wcol = wid >> 2;

            float acc[10][4];
            #pragma unroll
            for (int n = 0; n < 10; n++) {
                #pragma unroll
                for (int q = 0; q < 4; q++) acc[n][q] = 0.f;
            }
            const unsigned int aaddr = smem_u32(As) +
                (unsigned int)(((wr * 16 + (lane & 15)) * 24 + (lane >> 4) * 8) * 2);
            const unsigned int baddr = smem_u32(Bs) +
                (unsigned int)(((lane & 15) * 168) * 2);

            for (int kk = 0; kk < 18; kk++) {
                const int k0 = kbase + kk * 16;
                #pragma unroll
                for (int q = 0; q < 2; q++) {
                    int idx = t + q * 256;
                    int r = idx >> 3;
                    int c = (idx & 7) * 2;
                    *(uint32_t*)(As + r * 24 + c) =
                        *(const uint32_t*)(g_xh + (size_t)(m0 + r) * KD + k0 + c);
                }
                #pragma unroll
                for (int q = 0; q < 3; q++) {
                    int e = t + q * 256;
                    if (e < 640) {
                        int r = e / 40;
                        int c8 = e - r * 40;
                        *(uint2*)(Bs + r * 168 + c8 * 4) =
                            *(const uint2*)(g_wc + (size_t)(k0 + r) * JO + c8 * 4);
                    }
                }
                __syncthreads();
                unsigned int a0, a1, a2, a3;
                ldsm_x4(a0, a1, a2, a3, aaddr);
                #pragma unroll
                for (int nt = 0; nt < 10; nt++) {
                    unsigned int b0, b1;
                    ldsm_x2t(b0, b1, baddr + (unsigned int)((wcol * 80 + nt * 8) * 2));
                    mma16816(acc[nt], a0, a1, a2, a3, b0, b1);
                }
                __syncthreads();
            }
            const int g = lane >> 2;
            const int c2 = (lane & 3) * 2;
            float* base = g_s + (size_t)m0 * JO;
            #pragma unroll
            for (int nt = 0; nt < 10; nt++) {
                int col = wcol * 80 + nt * 8 + c2;
                int row = wr * 16 + g;
                atomicAdd(base + (size_t)row * JO + col,           acc[nt][0]);
                atomicAdd(base + (size_t)row * JO + col + 1,       acc[nt][1]);
                atomicAdd(base + (size_t)(row + 8) * JO + col,     acc[nt][2]);
                atomicAdd(base + (size_t)(row + 8) * JO + col + 1, acc[nt][3]);
            }
        }
        grid_barrier();

        // ================= P2: squash =================
        {
            float* red = (float*)smbuf;
            #pragma unroll
            for (int bb = 0; bb < 2; bb++) {
                const int b = blk * 2 + bb;
                __syncthreads();
                float s = 0.f;
                if (t < 160) {
                    s = g_s[b * JO + t];
                    red[t] = s * s;
                }
                __syncthreads();
                if (t < 160) {
                    const int base = (t >> 4) << 4;
                    float sq = 0.f;
                    #pragma unroll
                    for (int o = 0; o < 16; o++) sq += red[base + o];
                    float fac = (sq / (1.f + sq)) * rsqrtf(sq + 1e-9f);
                    float v = s * fac;
                    if (it < 2) {
                        g_vh[b * JO + t] = __float2half(v);
                        g_s[b * JO + t] = 0.f;
                    } else {
                        out[b * JO + t] = v;
                    }
                }
            }
        }
        if (it == 2) return;
        grid_barrier();

        // ================= P3: gemm_m + route =================
        if (blk < 72) {
            __half* As = (__half*)smbuf;
            __half* Bs = (__half*)(smbuf + 6144);
            float* sa = (float*)(smbuf + 11520);
            float* sc = (float*)(smbuf + 12160);
            const int m0 = blk * 128;
            const int i0 = blk * 16;

            float acc[20][4];
            #pragma unroll
            for (int n = 0; n < 20; n++) {
                #pragma unroll
                for (int q = 0; q < 4; q++) acc[n][q] = 0.f;
            }
            const unsigned int aaddr = smem_u32(As) +
                (unsigned int)(((wid * 16 + (lane & 15)) * 24 + (lane >> 4) * 8) * 2);
            const unsigned int baddr = smem_u32(Bs) +
                (unsigned int)(((lane & 15) * 168) * 2);

            for (int kk = 0; kk < 16; kk++) {
                const int k0 = kk * 16;
                #pragma unroll
                for (int q = 0; q < 4; q++) {
                    int idx = t + q * 256;
                    int r = idx >> 3;
                    int c = (idx & 7) * 2;
                    *(uint32_t*)(As + r * 24 + c) =
                        *(const uint32_t*)(g_xt + (size_t)(m0 + r) * BB + k0 + c);
                }
                #pragma unroll
                for (int q = 0; q < 3; q++) {
                    int e = t + q * 256;
                    if (e < 640) {
                        int r = e / 40;
                        int c8 = e - r * 40;
                        *(uint2*)(Bs + r * 168 + c8 * 4) =
                            *(const uint2*)(g_vh + (size_t)(k0 + r) * JO + c8 * 4);
                    }
                }
                __syncthreads();
                unsigned int a0, a1, a2, a3;
                ldsm_x4(a0, a1, a2, a3, aaddr);
                #pragma unroll
                for (int nt = 0; nt < 20; nt++) {
                    unsigned int b0, b1;
                    ldsm_x2t(b0, b1, baddr + (unsigned int)((nt * 8) * 2));
                    mma16816(acc[nt], a0, a1, a2, a3, b0, b1);
                }
                __syncthreads();
            }

            // route epilogue: agreement dot with Wt, warp-reduce.
            const int g = lane >> 2;
            const int c2 = (lane & 3) * 2;
            const int r1 = m0 + wid * 16 + g;
            const int r2 = r1 + 8;
            float p0[10];
            float p1[10];
            #pragma unroll
            for (int j = 0; j < 10; j++) { p0[j] = 0.f; p1[j] = 0.f; }
            #pragma unroll
            for (int nt = 0; nt < 20; nt++) {
                int col = nt * 8 + c2;
                int j = nt >> 1;
                __half2 w1 = *(const __half2*)(g_wt + (size_t)r1 * JO + col);
                __half2 w2 = *(const __half2*)(g_wt + (size_t)r2 * JO + col);
                float2 f1 = __half22float2(w1);
                float2 f2 = __half22float2(w2);
                p0[j] += acc[nt][0] * f1.x + acc[nt][1] * f1.y;
                p1[j] += acc[nt][2] * f2.x + acc[nt][3] * f2.y;
            }
            #pragma unroll
            for (int j = 0; j < 10; j++) {
                #pragma unroll
                for (int off = 16; off > 0; off >>= 1) {
                    p0[j] += __shfl_xor_sync(0xffffffffu, p0[j], off);
                    p1[j] += __shfl_xor_sync(0xffffffffu, p1[j], off);
                }
            }
            if (lane == 0) {
                #pragma unroll
                for (int j = 0; j < 10; j++) {
                    sa[(wid * 2) * 10 + j] = p0[j];
                    sa[(wid * 2 + 1) * 10 + j] = p1[j];
                }
            }
            __syncthreads();
            if (t < 16) {
                const int i = i0 + t;
                float bl[10];
                float ex[10];
                float mx = -1e30f;
                #pragma unroll
                for (int j = 0; j < 10; j++) {
                    float nb = g_blog[i * 10 + j] + sa[t * 10 + j] * (1.0f / 256.0f);
                    g_blog[i * 10 + j] = nb;
                    bl[j] = nb;
                    mx = fmaxf(mx, nb);
                }
                float sum = 0.f;
                #pragma unroll
                for (int j = 0; j < 10; j++) {
                    ex[j] = expf(bl[j] - mx);
                    sum += ex[j];
                }
                float inv = 1.f / sum;
                #pragma unroll
                for (int j = 0; j < 10; j++) {
                    sc[t * 10 + j] = ex[j] * inv;
                }
            }
            __syncthreads();
            // write Wc = c * Wt for this block's 128 rows.
            #pragma unroll
            for (int q = 0; q < 20; q++) {
                int e = t + q * 256;
                int r = e / 40;
                int c8 = e - r * 40;
                int j = c8 >> 2;
                float cw = sc[(r >> 3) * 10 + j];
                uint2 raw = *(const uint2*)(g_wt + (size_t)(m0 + r) * JO + c8 * 4);
                __half2 h0 = *(__half2*)&raw.x;
                __half2 h1 = *(__half2*)&raw.y;
                float2 f0 = __half22float2(h0);
                float2 f1 = __half22float2(h1);
                __half2 o0 = __floats2half2_rn(cw * f0.x, cw * f0.y);
                __half2 o1 = __floats2half2_rn(cw * f1.x, cw * f1.y);
                uint2 outv;
                outv.x = *(unsigned int*)&o0;
                outv.y = *(unsigned int*)&o1;
                *(uint2*)(g_wc + (size_t)(m0 + r) * JO + c8 * 4) = outv;
            }
        }
        grid_barrier();
    }
}

extern "C" void kernel_launch(void* const* d_in, const int* in_sizes, int n_in,
                              void* d_out, int out_size) {
    const float* x = (const float*)d_in[0];
    const float* w = (const float*)d_in[1];
    if (n_in >= 2 && in_sizes[0] == NIN * NOUT * DOUT * DIN
                  && in_sizes[1] == BB * DIN * NIN) {
        const float* tmp = x;
        x = w;
        w = tmp;
    }
    float* out = (float*)d_out;
    k_mega<<<NB, 256>>>(x, w, out);
}